// round 1
// baseline (speedup 1.0000x reference)
#include <cuda_runtime.h>

// Problem constants (B=4, N_obj=8 -> 32 objects, N_v=2048 points, 64 anchors, 16-NN)
#define N_V        2048
#define N_OBJS     32
#define ANCHORS    64
#define KNN        16
#define FPS_THREADS 256
#define PPT        8            // points per thread in FPS (2048/256)
#define FULL       0xffffffffu

__device__ int g_anchors[N_OBJS * ANCHORS];

// ---------------------------------------------------------------------------
// Kernel 1: farthest point sampling, one block per object.
// Points cached in SMEM; each thread owns 8 points (coords + running min-dist
// in registers). One barrier per iteration via double-buffered warp partials.
// ---------------------------------------------------------------------------
__global__ __launch_bounds__(FPS_THREADS) void fps_kernel(const float* __restrict__ pos) {
    const int o = blockIdx.x;
    const float* __restrict__ P = pos + (size_t)o * N_V * 3;

    __shared__ float spts[N_V * 3];                       // 24 KB
    __shared__ unsigned long long swk[2][FPS_THREADS / 32];

    const int tid  = threadIdx.x;
    const int lane = tid & 31;
    const int wid  = tid >> 5;

    for (int i = tid; i < N_V * 3; i += FPS_THREADS) spts[i] = P[i];
    __syncthreads();

    float px[PPT], py[PPT], pz[PPT], md[PPT];
    const float x0 = spts[0], y0 = spts[1], z0 = spts[2];
#pragma unroll
    for (int k = 0; k < PPT; k++) {
        const int j = tid + FPS_THREADS * k;
        px[k] = spts[j * 3 + 0];
        py[k] = spts[j * 3 + 1];
        pz[k] = spts[j * 3 + 2];
        const float dx = px[k] - x0, dy = py[k] - y0, dz = pz[k] - z0;
        md[k] = dx * dx + dy * dy + dz * dz;              // matches reference FPS formula
    }
    if (tid == 0) g_anchors[o * ANCHORS + 0] = 0;

    int buf = 0;
    for (int it = 1; it < ANCHORS; ++it) {
        // local argmax over my 8 points
        float bv = md[0];
        int   bi = tid;
#pragma unroll
        for (int k = 1; k < PPT; k++) {
            if (md[k] > bv) { bv = md[k]; bi = tid + FPS_THREADS * k; }
        }
        // warp argmax: md >= 0 so raw float bits are monotonic as unsigned
        const unsigned u = __float_as_uint(bv);
        const unsigned m = __reduce_max_sync(FULL, u);
        const unsigned bal = __ballot_sync(FULL, u == m);
        const int src = __ffs(bal) - 1;
        const int ci  = __shfl_sync(FULL, bi, src);
        if (lane == 0)
            swk[buf][wid] = ((unsigned long long)m << 32) | (unsigned)(0x7FFFFFFF - ci);
        __syncthreads();

        // every thread reduces the 8 warp partials (no second barrier needed)
        unsigned long long best = swk[buf][0];
#pragma unroll
        for (int w = 1; w < FPS_THREADS / 32; w++) {
            const unsigned long long c = swk[buf][w];
            if (c > best) best = c;
        }
        const int bidx = 0x7FFFFFFF - (int)(unsigned)(best & 0xFFFFFFFFull);
        if (tid == 0) g_anchors[o * ANCHORS + it] = bidx;

        const float qx = spts[bidx * 3 + 0];
        const float qy = spts[bidx * 3 + 1];
        const float qz = spts[bidx * 3 + 2];
#pragma unroll
        for (int k = 0; k < PPT; k++) {
            const float dx = px[k] - qx, dy = py[k] - qy, dz = pz[k] - qz;
            const float d = dx * dx + dy * dy + dz * dz;
            md[k] = fminf(md[k], d);
        }
        buf ^= 1;
    }
}

// monotonic total-order key for floats (handles tiny negative d2 from cancellation)
__device__ __forceinline__ unsigned fkey(float f) {
    const unsigned u = __float_as_uint(f);
    return (u & 0x80000000u) ? ~u : (u | 0x80000000u);
}

// ---------------------------------------------------------------------------
// Kernel 2: KNN (only at anchors) + gather + output assembly.
// One warp per (object, anchor). Each lane scans 64 points keeping a
// register-resident top-16 (replace-max, static indexing only), then a
// 16-round warp merge extracts the global 16 nearest.
// ---------------------------------------------------------------------------
__global__ __launch_bounds__(128) void knn_kernel(const float* __restrict__ pos,
                                                  const float* __restrict__ vel,
                                                  const float* __restrict__ phys,
                                                  const float* __restrict__ refp,
                                                  float* __restrict__ out) {
    const int w    = blockIdx.x * 4 + (threadIdx.x >> 5);   // global anchor id [0,2048)
    const int lane = threadIdx.x & 31;
    const int obj  = w >> 6;
    const int aidx = g_anchors[w];

    const float* __restrict__ P = pos + (size_t)obj * N_V * 3;
    const float qx = P[aidx * 3 + 0];
    const float qy = P[aidx * 3 + 1];
    const float qz = P[aidx * 3 + 2];
    const float sqq = qx * qx + qy * qy + qz * qz;

    float v[KNN];
    int   ix[KNN];

    // first 16 points fill the list directly
#pragma unroll
    for (int k = 0; k < KNN; k++) {
        const int j = k * 32 + lane;
        const float x = P[j * 3 + 0], y = P[j * 3 + 1], z = P[j * 3 + 2];
        float d = (x * x + y * y + z * z + sqq) - 2.0f * (x * qx + y * qy + z * qz);
        if (j == aidx) d += 1e10f;                        // reference's diagonal exclusion
        v[k] = d; ix[k] = j;
    }
    float worst = v[0];
#pragma unroll
    for (int t = 1; t < KNN; t++) worst = fmaxf(worst, v[t]);

#pragma unroll 4
    for (int k = KNN; k < 64; k++) {
        const int j = k * 32 + lane;
        const float x = P[j * 3 + 0], y = P[j * 3 + 1], z = P[j * 3 + 2];
        float d = (x * x + y * y + z * z + sqq) - 2.0f * (x * qx + y * qy + z * qz);
        if (j == aidx) d += 1e10f;
        if (d < worst) {
            bool done = false;
#pragma unroll
            for (int t = 0; t < KNN; t++) {               // replace first slot holding 'worst'
                const bool h = (!done) && (v[t] == worst);
                if (h) { v[t] = d; ix[t] = j; }
                done = done || h;
            }
            worst = v[0];
#pragma unroll
            for (int t = 1; t < KNN; t++) worst = fmaxf(worst, v[t]);
        }
    }

    // warp merge: 16 rounds of argmin over the 32 lane-local lists
    const float FINF = __int_as_float(0x7f800000);
    int saved = 0;                                        // lane r keeps round-r winner
#pragma unroll
    for (int r = 0; r < KNN; r++) {
        float lm = v[0]; int li = ix[0]; int ls = 0;
#pragma unroll
        for (int t = 1; t < KNN; t++) {
            if (v[t] < lm) { lm = v[t]; li = ix[t]; ls = t; }
        }
        const unsigned key = fkey(lm);
        const unsigned km  = __reduce_min_sync(FULL, key);
        const unsigned bal = __ballot_sync(FULL, key == km);
        const int win  = __ffs(bal) - 1;
        const int widx = __shfl_sync(FULL, li, win);
        if (lane == win) {
#pragma unroll
            for (int t = 0; t < KNN; t++) { if (t == ls) v[t] = FINF; }
        }
        if (lane == r) saved = widx;
    }

    // sum the 16 neighbor positions (lanes 0..15 hold the winners)
    float nx = 0.f, ny = 0.f, nz = 0.f;
    if (lane < KNN) {
        nx = P[saved * 3 + 0];
        ny = P[saved * 3 + 1];
        nz = P[saved * 3 + 2];
    }
#pragma unroll
    for (int off = 16; off; off >>= 1) {
        nx += __shfl_xor_sync(FULL, nx, off);
        ny += __shfl_xor_sync(FULL, ny, off);
        nz += __shfl_xor_sync(FULL, nz, off);
    }

    if (lane == 0) {
        float* __restrict__ o = out + (size_t)w * 12;
        const float inv = 1.0f / 16.0f;
        // anchor_dist: mean(neigh) - p
        o[0] = nx * inv - qx;
        o[1] = ny * inv - qy;
        o[2] = nz * inv - qz;
        // anchor_vel
        const float* __restrict__ V = vel + (size_t)obj * N_V * 3;
        o[3] = V[aidx * 3 + 0];
        o[4] = V[aidx * 3 + 1];
        o[5] = V[aidx * 3 + 2];
        // anchor_rel = pos - ref
        const float* __restrict__ R = refp + (size_t)obj * N_V * 3;
        o[6] = qx - R[aidx * 3 + 0];
        o[7] = qy - R[aidx * 3 + 1];
        o[8] = qz - R[aidx * 3 + 2];
        // physics broadcast
        o[9]  = phys[obj * 3 + 0];
        o[10] = phys[obj * 3 + 1];
        o[11] = phys[obj * 3 + 2];
    }
}

extern "C" void kernel_launch(void* const* d_in, const int* in_sizes, int n_in,
                              void* d_out, int out_size) {
    const float* positions  = (const float*)d_in[0];
    const float* velocities = (const float*)d_in[1];
    const float* physics    = (const float*)d_in[2];
    const float* refpos     = (const float*)d_in[3];
    float* out = (float*)d_out;

    fps_kernel<<<N_OBJS, FPS_THREADS>>>(positions);
    knn_kernel<<<(N_OBJS * ANCHORS) / 4, 128>>>(positions, velocities, physics, refpos, out);
}

// round 2
// speedup vs baseline: 1.3793x; 1.3793x over previous
#include <cuda_runtime.h>

// Problem constants (B=4, N_obj=8 -> 32 objects, N_v=2048 points, 64 anchors, 16-NN)
#define N_V        2048
#define N_OBJS     32
#define ANCHORS    64
#define KNN        16
#define FPS_THREADS 256
#define PPT        8            // points per thread in FPS (2048/256)
#define FULL       0xffffffffu

__device__ int g_anchors[N_OBJS * ANCHORS];

// ---------------------------------------------------------------------------
// Kernel 1: farthest point sampling, one block per object.
// Points cached in SMEM; each thread owns 8 points (coords + running min-dist
// in registers). One barrier per iteration via double-buffered warp partials.
// ---------------------------------------------------------------------------
__global__ __launch_bounds__(FPS_THREADS) void fps_kernel(const float* __restrict__ pos) {
    const int o = blockIdx.x;
    const float* __restrict__ P = pos + (size_t)o * N_V * 3;

    __shared__ float spts[N_V * 3];                       // 24 KB
    __shared__ unsigned long long swk[2][FPS_THREADS / 32];

    const int tid  = threadIdx.x;
    const int lane = tid & 31;
    const int wid  = tid >> 5;

    for (int i = tid; i < N_V * 3; i += FPS_THREADS) spts[i] = P[i];
    __syncthreads();

    float px[PPT], py[PPT], pz[PPT], md[PPT];
    const float x0 = spts[0], y0 = spts[1], z0 = spts[2];
#pragma unroll
    for (int k = 0; k < PPT; k++) {
        const int j = tid + FPS_THREADS * k;
        px[k] = spts[j * 3 + 0];
        py[k] = spts[j * 3 + 1];
        pz[k] = spts[j * 3 + 2];
        const float dx = px[k] - x0, dy = py[k] - y0, dz = pz[k] - z0;
        md[k] = dx * dx + dy * dy + dz * dz;              // matches reference FPS formula
    }
    if (tid == 0) g_anchors[o * ANCHORS + 0] = 0;

    int buf = 0;
    for (int it = 1; it < ANCHORS; ++it) {
        // local argmax over my 8 points
        float bv = md[0];
        int   bi = tid;
#pragma unroll
        for (int k = 1; k < PPT; k++) {
            if (md[k] > bv) { bv = md[k]; bi = tid + FPS_THREADS * k; }
        }
        // warp argmax: md >= 0 so raw float bits are monotonic as unsigned
        const unsigned u = __float_as_uint(bv);
        const unsigned m = __reduce_max_sync(FULL, u);
        const unsigned bal = __ballot_sync(FULL, u == m);
        const int src = __ffs(bal) - 1;
        const int ci  = __shfl_sync(FULL, bi, src);
        if (lane == 0)
            swk[buf][wid] = ((unsigned long long)m << 32) | (unsigned)(0x7FFFFFFF - ci);
        __syncthreads();

        // every thread reduces the 8 warp partials (no second barrier needed)
        unsigned long long best = swk[buf][0];
#pragma unroll
        for (int w = 1; w < FPS_THREADS / 32; w++) {
            const unsigned long long c = swk[buf][w];
            if (c > best) best = c;
        }
        const int bidx = 0x7FFFFFFF - (int)(unsigned)(best & 0xFFFFFFFFull);
        if (tid == 0) g_anchors[o * ANCHORS + it] = bidx;

        const float qx = spts[bidx * 3 + 0];
        const float qy = spts[bidx * 3 + 1];
        const float qz = spts[bidx * 3 + 2];
#pragma unroll
        for (int k = 0; k < PPT; k++) {
            const float dx = px[k] - qx, dy = py[k] - qy, dz = pz[k] - qz;
            const float d = dx * dx + dy * dy + dz * dz;
            md[k] = fminf(md[k], d);
        }
        buf ^= 1;
    }
}

// monotonic total-order key for floats (handles tiny negative d2 from cancellation)
__device__ __forceinline__ unsigned fkey(float f) {
    const unsigned u = __float_as_uint(f);
    return (u & 0x80000000u) ? ~u : (u | 0x80000000u);
}

// ---------------------------------------------------------------------------
// Kernel 2: KNN at anchors + gather + output assembly.
// One BLOCK (4 warps) per anchor. Each lane owns exactly 16 points, so no
// online top-k maintenance is needed: lane sorts its 16 distances (bitonic,
// value-only), each warp pop-min-extracts its 16 smallest, warp 0 merges the
// 64 candidates to the global 16th-smallest threshold T, and all threads
// accumulate positions of points with d <= T.
// ---------------------------------------------------------------------------
__global__ __launch_bounds__(128) void knn_kernel(const float* __restrict__ pos,
                                                  const float* __restrict__ vel,
                                                  const float* __restrict__ phys,
                                                  const float* __restrict__ refp,
                                                  float* __restrict__ out) {
    const int a    = blockIdx.x;                 // global anchor id [0, 2048)
    const int tid  = threadIdx.x;
    const int lane = tid & 31;
    const int wid  = tid >> 5;
    const int obj  = a >> 6;
    const int aidx = g_anchors[a];

    const float* __restrict__ P = pos + (size_t)obj * N_V * 3;
    const float qx = P[aidx * 3 + 0];
    const float qy = P[aidx * 3 + 1];
    const float qz = P[aidx * 3 + 2];
    const float sqq = qx * qx + qy * qy + qz * qz;

    const int base = wid << 9;                   // this warp's 512-point chunk

    // ---- distances for my 16 points (kept in d[]; v[] is scratch) ----
    float d[KNN], v[KNN];
#pragma unroll
    for (int k = 0; k < KNN; k++) {
        const int j = base + (k << 5) + lane;
        const float x = P[j * 3 + 0], y = P[j * 3 + 1], z = P[j * 3 + 2];
        float t1 = fmaf(x, x, sqq); t1 = fmaf(y, y, t1); t1 = fmaf(z, z, t1);
        float t2 = x * qx; t2 = fmaf(y, qy, t2); t2 = fmaf(z, qz, t2);
        float dd = fmaf(t2, -2.0f, t1);
        if (j == aidx) dd += 1e10f;              // reference's diagonal exclusion
        d[k] = dd; v[k] = dd;
    }

    // ---- bitonic sort of the 16 values (ascending), value-only ----
#pragma unroll
    for (int kk = 2; kk <= KNN; kk <<= 1) {
#pragma unroll
        for (int jj = kk >> 1; jj > 0; jj >>= 1) {
#pragma unroll
            for (int i = 0; i < KNN; i++) {
                const int l = i ^ jj;
                if (l > i) {
                    const float va = v[i], vb = v[l];
                    const float lo = fminf(va, vb), hi = fmaxf(va, vb);
                    const bool up = ((i & kk) == 0);
                    v[i] = up ? lo : hi;
                    v[l] = up ? hi : lo;
                }
            }
        }
    }

    // ---- per-warp pop-min extraction: 16 smallest of this warp's 512 ----
    __shared__ float cand[4 * KNN];
    __shared__ float sT;
    __shared__ float psum[4][3];
    const float FINF = __int_as_float(0x7f800000);

#pragma unroll
    for (int r = 0; r < KNN; r++) {
        const unsigned key  = fkey(v[0]);
        const unsigned kmin = __reduce_min_sync(FULL, key);
        const unsigned bal  = __ballot_sync(FULL, key == kmin);
        const int win = __ffs(bal) - 1;
        if (lane == win) {
            cand[(wid << 4) + r] = v[0];
#pragma unroll
            for (int t = 0; t < KNN - 1; t++) v[t] = v[t + 1];
            v[KNN - 1] = FINF;
        }
    }
    __syncthreads();

    // ---- warp 0: global threshold T = 16th smallest of the 64 candidates ----
    if (wid == 0) {
        float c0 = cand[lane * 2], c1 = cand[lane * 2 + 1];
        const float lo = fminf(c0, c1), hi = fmaxf(c0, c1);
        c0 = lo; c1 = hi;
        float T = 0.0f;
#pragma unroll
        for (int r = 0; r < KNN; r++) {
            const unsigned key  = fkey(c0);
            const unsigned kmin = __reduce_min_sync(FULL, key);
            const unsigned bal  = __ballot_sync(FULL, key == kmin);
            const int win = __ffs(bal) - 1;
            T = __shfl_sync(FULL, c0, win);
            if (lane == win) { c0 = c1; c1 = FINF; }
        }
        if (lane == 0) sT = T;
    }
    __syncthreads();
    const float T = sT;

    // ---- accumulate positions of the 16 selected points ----
    float sx = 0.f, sy = 0.f, sz = 0.f;
#pragma unroll
    for (int k = 0; k < KNN; k++) {
        if (d[k] <= T) {
            const int j = base + (k << 5) + lane;
            sx += P[j * 3 + 0];
            sy += P[j * 3 + 1];
            sz += P[j * 3 + 2];
        }
    }
#pragma unroll
    for (int off = 16; off; off >>= 1) {
        sx += __shfl_xor_sync(FULL, sx, off);
        sy += __shfl_xor_sync(FULL, sy, off);
        sz += __shfl_xor_sync(FULL, sz, off);
    }
    if (lane == 0) { psum[wid][0] = sx; psum[wid][1] = sy; psum[wid][2] = sz; }
    __syncthreads();

    if (tid == 0) {
        const float nx = psum[0][0] + psum[1][0] + psum[2][0] + psum[3][0];
        const float ny = psum[0][1] + psum[1][1] + psum[2][1] + psum[3][1];
        const float nz = psum[0][2] + psum[1][2] + psum[2][2] + psum[3][2];
        float* __restrict__ o = out + (size_t)a * 12;
        const float inv = 1.0f / 16.0f;
        // anchor_dist: mean(neigh) - p
        o[0] = nx * inv - qx;
        o[1] = ny * inv - qy;
        o[2] = nz * inv - qz;
        // anchor_vel
        const float* __restrict__ V = vel + (size_t)obj * N_V * 3;
        o[3] = V[aidx * 3 + 0];
        o[4] = V[aidx * 3 + 1];
        o[5] = V[aidx * 3 + 2];
        // anchor_rel = pos - ref
        const float* __restrict__ R = refp + (size_t)obj * N_V * 3;
        o[6] = qx - R[aidx * 3 + 0];
        o[7] = qy - R[aidx * 3 + 1];
        o[8] = qz - R[aidx * 3 + 2];
        // physics broadcast
        o[9]  = phys[obj * 3 + 0];
        o[10] = phys[obj * 3 + 1];
        o[11] = phys[obj * 3 + 2];
    }
}

extern "C" void kernel_launch(void* const* d_in, const int* in_sizes, int n_in,
                              void* d_out, int out_size) {
    const float* positions  = (const float*)d_in[0];
    const float* velocities = (const float*)d_in[1];
    const float* physics    = (const float*)d_in[2];
    const float* refpos     = (const float*)d_in[3];
    float* out = (float*)d_out;

    fps_kernel<<<N_OBJS, FPS_THREADS>>>(positions);
    knn_kernel<<<N_OBJS * ANCHORS, 128>>>(positions, velocities, physics, refpos, out);
}